// round 15
// baseline (speedup 1.0000x reference)
#include <cuda_runtime.h>
#include <cstdint>
#include <math.h>

// CT-GRU round 15: two-level INT8 GEMMs (mma.m16n8k32.s8), phased single-pass.
#define BB 2048
#define UU 512
#define MM 8
#define DD 512
#define RU 4096
#define AROW 2048            // [a0(1024) | a1(1024)]
#define WROW 3072            // [w0 | w1 | w0]
#define LN_TAU_STEP 1.1512925464970229f

__device__ int8_t g_Af[(size_t)BB * AROW];
__device__ int8_t g_Ar[(size_t)BB * AROW];
__device__ int8_t g_Wr[(size_t)RU * WROW];
__device__ int8_t g_Wu[(size_t)RU * WROW];
__device__ int8_t g_Wd[(size_t)UU * WROW];
__device__ float  g_alF[BB], g_alR[BB];
__device__ float  g_beR[RU], g_beU[RU], g_beD[UU];
__device__ float  g_r[(size_t)BB * RU];      // ln_tau_r (final)
__device__ float  g_u[(size_t)BB * RU];      // ln_tau_s (final)
__device__ float  g_pd[3 * (size_t)BB * UU]; // D-GEMM slice partials

__device__ __forceinline__ uint32_t smem_u32(const void* p) {
    uint32_t a;
    asm("{ .reg .u64 t; cvta.to.shared.u64 t, %1; cvt.u32.u64 %0, t; }"
        : "=r"(a) : "l"(p));
    return a;
}
__device__ __forceinline__ void ldsm_x4(uint32_t* r, uint32_t addr) {
    asm volatile("ldmatrix.sync.aligned.m8n8.x4.shared.b16 {%0,%1,%2,%3}, [%4];"
        : "=r"(r[0]), "=r"(r[1]), "=r"(r[2]), "=r"(r[3]) : "r"(addr));
}
__device__ __forceinline__ void mma_s8(int* d, const uint32_t* a,
                                       uint32_t b0, uint32_t b1) {
    asm volatile("mma.sync.aligned.m16n8k32.row.col.s32.s8.s8.s32 "
        "{%0,%1,%2,%3}, {%4,%5,%6,%7}, {%8,%9}, {%0,%1,%2,%3};"
        : "+r"(d[0]), "+r"(d[1]), "+r"(d[2]), "+r"(d[3])
        : "r"(a[0]), "r"(a[1]), "r"(a[2]), "r"(a[3]), "r"(b0), "r"(b1));
}
__device__ __forceinline__ void cp16(uint32_t dst, const void* src) {
    asm volatile("cp.async.cg.shared.global [%0], [%1], 16;" :: "r"(dst), "l"(src));
}
#define CP_COMMIT() asm volatile("cp.async.commit_group;" ::: "memory")
#define CP_WAIT(n)  asm volatile("cp.async.wait_group %0;" :: "n"(n) : "memory")

__device__ __forceinline__ uint32_t swz(int row, int chunk) {
    return (uint32_t)(row * 128 + ((chunk ^ (row & 7)) << 4));
}
// v ~ a*(c0 + c1/256)
__device__ __forceinline__ void quant2(float v, float a, float inva,
                                       int8_t& c0, int8_t& c1) {
    int i0 = __float2int_rn(v * inva);
    i0 = max(-127, min(127, i0));
    int i1 = __float2int_rn((v - a * (float)i0) * inva * 256.0f);
    i1 = max(-127, min(127, i1));
    c0 = (int8_t)i0; c1 = (int8_t)i1;
}

// ---------------------------------------------------------------------------
// quant_setup: blocks [0,272) weight quant (Wr 128, Wu 128, Wd 16);
//              blocks [272,2320) per-batch-row A quant + prep. 256 threads.
// ---------------------------------------------------------------------------
__global__ void quant_setup_kernel(const float* __restrict__ inputs,
                                   const float* __restrict__ state,
                                   const float* __restrict__ W_r,
                                   const float* __restrict__ W_u,
                                   const float* __restrict__ W_d)
{
    __shared__ float shf[512];
    __shared__ float shbe[32];
    __shared__ __align__(4) int8_t sht[2048];
    const int bid = blockIdx.x;
    const int t = threadIdx.x;

    if (bid < 272) {
        const float* W; int8_t* Wt; float* beta; int N; int n0;
        if (bid < 128)      { W = W_r; Wt = g_Wr; beta = g_beR; N = RU; n0 = bid * 32; }
        else if (bid < 256) { W = W_u; Wt = g_Wu; beta = g_beU; N = RU; n0 = (bid - 128) * 32; }
        else                { W = W_d; Wt = g_Wd; beta = g_beD; N = UU; n0 = (bid - 256) * 32; }
        const int c = t & 31, rg = t >> 5;
        float m = 0.0f;
        for (int k = rg; k < 1024; k += 8)
            m = fmaxf(m, fabsf(W[(size_t)k * N + n0 + c]));
        shf[rg * 32 + c] = m;
        __syncthreads();
        if (rg == 0) {
#pragma unroll
            for (int i = 1; i < 8; i++) m = fmaxf(m, shf[i * 32 + c]);
            float be = fmaxf(m, 1e-30f) * (1.0f / 127.0f);
            beta[n0 + c] = be;
            shbe[c] = be;
        }
        __syncthreads();
        const float be = shbe[c], inv = 1.0f / be;
        for (int k0 = 0; k0 < 1024; k0 += 32) {
#pragma unroll
            for (int i = 0; i < 4; i++) {
                int kl = rg + i * 8;
                int8_t q0, q1;
                quant2(W[(size_t)(k0 + kl) * N + n0 + c], be, inv, q0, q1);
                sht[c * 32 + kl] = q0;
                sht[1024 + c * 32 + kl] = q1;
            }
            __syncthreads();
            int nl = t >> 3, bg = (t & 7) * 4;
            int w0v = *(int*)&sht[nl * 32 + bg];
            int w1v = *(int*)&sht[1024 + nl * 32 + bg];
            size_t wb = (size_t)(n0 + nl) * WROW + k0 + bg;
            *(int*)(Wt + wb)        = w0v;
            *(int*)(Wt + wb + 1024) = w1v;
            *(int*)(Wt + wb + 2048) = w0v;
            __syncthreads();
        }
        return;
    }

    // A-side: one batch row per block; thread t handles units t and t+256.
    const int b = bid - 272;
    float x0 = inputs[(size_t)b * DD + t];
    float x1 = inputs[(size_t)b * DD + 256 + t];
    const float* sp = state + (size_t)b * RU;
    float4 s0 = *(const float4*)(sp + t * 8);
    float4 s1 = *(const float4*)(sp + t * 8 + 4);
    float4 s2 = *(const float4*)(sp + (t + 256) * 8);
    float4 s3 = *(const float4*)(sp + (t + 256) * 8 + 4);
    float h0 = ((s0.x + s0.y) + (s0.z + s0.w)) + ((s1.x + s1.y) + (s1.z + s1.w));
    float h1 = ((s2.x + s2.y) + (s2.z + s2.w)) + ((s3.x + s3.y) + (s3.z + s3.w));
    float mS = fmaxf(fmaxf(fmaxf(fabsf(s0.x), fabsf(s0.y)), fmaxf(fabsf(s0.z), fabsf(s0.w))),
                     fmaxf(fmaxf(fabsf(s1.x), fabsf(s1.y)), fmaxf(fabsf(s1.z), fabsf(s1.w))));
    mS = fmaxf(mS, fmaxf(fmaxf(fmaxf(fabsf(s2.x), fabsf(s2.y)), fmaxf(fabsf(s2.z), fabsf(s2.w))),
                         fmaxf(fmaxf(fabsf(s3.x), fabsf(s3.y)), fmaxf(fabsf(s3.z), fabsf(s3.w)))));
    float mx = fmaxf(fabsf(x0), fabsf(x1));
    shf[t] = fmaxf(mx, fmaxf(fabsf(h0), fabsf(h1)));   // bound for [x|h]
    shf[256 + t] = fmaxf(mx, mS);                       // bound for [x|q], |q|<=max|state|
    __syncthreads();
    for (int s = 128; s > 0; s >>= 1) {
        if (t < s) {
            shf[t] = fmaxf(shf[t], shf[t + s]);
            shf[256 + t] = fmaxf(shf[256 + t], shf[256 + t + s]);
        }
        __syncthreads();
    }
    const float aF = fmaxf(shf[0], 1e-30f) * (1.0f / 127.0f);
    const float aR = fmaxf(shf[256], 1e-30f) * (1.0f / 127.0f);
    if (t == 0) { g_alF[b] = aF; g_alR[b] = aR; }
    const float iF = 1.0f / aF, iR = 1.0f / aR;
    size_t ba = (size_t)b * AROW;
    int8_t c0, c1;
    quant2(x0, aF, iF, c0, c1); g_Af[ba + t] = c0;       g_Af[ba + 1024 + t] = c1;
    quant2(x1, aF, iF, c0, c1); g_Af[ba + 256 + t] = c0; g_Af[ba + 1280 + t] = c1;
    quant2(h0, aF, iF, c0, c1); g_Af[ba + 512 + t] = c0; g_Af[ba + 1536 + t] = c1;
    quant2(h1, aF, iF, c0, c1); g_Af[ba + 768 + t] = c0; g_Af[ba + 1792 + t] = c1;
    quant2(x0, aR, iR, c0, c1); g_Ar[ba + t] = c0;       g_Ar[ba + 1024 + t] = c1;
    quant2(x1, aR, iR, c0, c1); g_Ar[ba + 256 + t] = c0; g_Ar[ba + 1280 + t] = c1;
}

// ---------------------------------------------------------------------------
// Phased int8 GEMM. BM=256, BN=128, BK=128 int8, 512 threads, warp tile 64x32.
// mode 0: z selects {W0,be0,bi0,C0}/{W1,...}; 24 iters; stash P0 at it==7;
//         C = alpha*beta*(P0 + P1/256) + bias.
// mode 1: W0 set; z slice (kbeg=8z, 8 iters); raw float acc -> C0 + z*B*U.
// ---------------------------------------------------------------------------
#define S8_STG 49152u
#define S8_SMEM (2u * S8_STG + 131072u)   // 229376

__global__ void __launch_bounds__(512, 1)
gemm_s8_kernel(const int8_t* __restrict__ A,
               const int8_t* __restrict__ W0, const int8_t* __restrict__ W1,
               const float* __restrict__ alpha,
               const float* __restrict__ be0, const float* __restrict__ be1,
               const float* __restrict__ bi0, const float* __restrict__ bi1,
               float* __restrict__ C0, float* __restrict__ C1,
               int Ndim, int mode)
{
    extern __shared__ char smem[];
    const uint32_t sb = smem_u32(smem);
    float* stash = (float*)(smem + 2 * S8_STG);
    const int tid = threadIdx.x;
    const int wid = tid >> 5;
    const int lane = tid & 31;
    const int bn = blockIdx.x * 128;
    const int bm = blockIdx.y * 256;
    const int z = blockIdx.z;

    const int8_t* Bt; const float* beta; const float* bias; float* C;
    int kbeg, kend, phased;
    if (mode == 0) {
        Bt = z ? W1 : W0; beta = z ? be1 : be0; bias = z ? bi1 : bi0;
        C = z ? C1 : C0; kbeg = 0; kend = 24; phased = 1;
    } else {
        Bt = W0; beta = be0; bias = nullptr;
        C = C0 + (size_t)z * ((size_t)BB * UU);
        kbeg = 8 * z; kend = kbeg + 8; phased = 0;
    }

    const int warp_m = (wid & 3) * 64;
    const int warp_n = (wid >> 2) * 32;

    int acc[4][4][4];
    int* af = &acc[0][0][0];
#pragma unroll
    for (int i = 0; i < 64; i++) af[i] = 0;

    // linearized loader: slot s: row = (tid>>3) + 64*s (row&7 invariant)
    const int r8 = tid >> 3, ch = tid & 7;
    const uint32_t dA = (uint32_t)(r8 * 128 + ((ch ^ (r8 & 7)) << 4));
    const uint32_t dB = 32768u + dA;
    const char* Ap = (const char*)A  + (size_t)(bm + r8) * AROW + ch * 16;
    const char* Bp = (const char*)Bt + (size_t)(bn + r8) * WROW + ch * 16;

    auto load_stage = [&](int it) {
        const uint32_t stg = sb + (uint32_t)((it - kbeg) & 1) * S8_STG;
        const int aoff = (it < 8 ? it : it - 8) << 7;
        const int woff = it << 7;
#pragma unroll
        for (int s = 0; s < 4; s++)
            cp16(stg + dA + (uint32_t)s * 8192u, Ap + aoff + (size_t)s * 64 * AROW);
#pragma unroll
        for (int s = 0; s < 2; s++)
            cp16(stg + dB + (uint32_t)s * 8192u, Bp + woff + (size_t)s * 64 * WROW);
        CP_COMMIT();
    };

    load_stage(kbeg);

#pragma unroll 1
    for (int it = kbeg; it < kend; it++) {
        CP_WAIT(0);
        __syncthreads();
        if (it + 1 < kend) load_stage(it + 1);

        const uint32_t abase = sb + (uint32_t)((it - kbeg) & 1) * S8_STG;
        const uint32_t bbase = abase + 32768u;
#pragma unroll
        for (int kk = 0; kk < 4; kk++) {          // 32 int8-K per step
            const int kch = kk * 2;
            uint32_t a[4][4];
#pragma unroll
            for (int mi = 0; mi < 4; mi++) {
                int row = warp_m + mi * 16 + (lane & 15);
                int c = kch + ((lane >> 4) & 1);
                ldsm_x4(a[mi], abase + swz(row, c));
            }
#pragma unroll
            for (int nb = 0; nb < 2; nb++) {
                uint32_t b[4];
                int row = warp_n + nb * 16 + (lane & 7) + (((lane >> 4) & 1) << 3);
                int c = kch + ((lane >> 3) & 1);
                ldsm_x4(b, bbase + swz(row, c));
#pragma unroll
                for (int mi = 0; mi < 4; mi++) {
                    mma_s8(acc[mi][nb * 2 + 0], a[mi], b[0], b[1]);
                    mma_s8(acc[mi][nb * 2 + 1], a[mi], b[2], b[3]);
                }
            }
        }
        if (phased && it == 7) {
            // stash exact phase-A partial (|P0| <= 1.65e7 < 2^24), reset acc
#pragma unroll
            for (int i = 0; i < 64; i++) { stash[i * 512 + tid] = (float)af[i]; af[i] = 0; }
        }
    }

    const int q  = lane & 3;
    const int rq = lane >> 2;
    if (phased) {
#pragma unroll
        for (int ni = 0; ni < 4; ni++) {
            int col = bn + warp_n + ni * 8 + q * 2;
            float be0v = beta[col], be1v = beta[col + 1];
            float bi0v = bias[col], bi1v = bias[col + 1];
#pragma unroll
            for (int mi = 0; mi < 4; mi++) {
                int rr = bm + warp_m + mi * 16 + rq;
                float alo = alpha[rr], ahi = alpha[rr + 8];
                int ix = mi * 16 + ni * 4;
                float p0 = stash[(ix + 0) * 512 + tid];
                float p1 = stash[(ix + 1) * 512 + tid];
                float p2 = stash[(ix + 2) * 512 + tid];
                float p3 = stash[(ix + 3) * 512 + tid];
                const float S = 1.0f / 256.0f;
                float2 v0, v1;
                v0.x = alo * be0v * (p0 + (float)acc[mi][ni][0] * S) + bi0v;
                v0.y = alo * be1v * (p1 + (float)acc[mi][ni][1] * S) + bi1v;
                v1.x = ahi * be0v * (p2 + (float)acc[mi][ni][2] * S) + bi0v;
                v1.y = ahi * be1v * (p3 + (float)acc[mi][ni][3] * S) + bi1v;
                *(float2*)(C + (size_t)rr * Ndim + col) = v0;
                *(float2*)(C + (size_t)(rr + 8) * Ndim + col) = v1;
            }
        }
    } else {
#pragma unroll
        for (int ni = 0; ni < 4; ni++) {
            int col = bn + warp_n + ni * 8 + q * 2;
#pragma unroll
            for (int mi = 0; mi < 4; mi++) {
                int rr = bm + warp_m + mi * 16 + rq;
                float2 v0 = make_float2((float)acc[mi][ni][0], (float)acc[mi][ni][1]);
                float2 v1 = make_float2((float)acc[mi][ni][2], (float)acc[mi][ni][3]);
                *(float2*)(C + (size_t)rr * Ndim + col) = v0;
                *(float2*)(C + (size_t)(rr + 8) * Ndim + col) = v1;
            }
        }
    }
}

// ---------------------------------------------------------------------------
// gate_r: softmax over buckets + q_input; quantize q into g_Ar [a0|a1] slots.
// ---------------------------------------------------------------------------
__global__ void gate_r_kernel(const float* __restrict__ state)
{
    int idx = blockIdx.x * blockDim.x + threadIdx.x;
    if (idx >= BB * UU) return;
    int b = idx >> 9;
    int u = idx & 511;

    const float* rp = g_r + (size_t)b * RU + u * MM;
    float x[8], h[8];
    *(float4*)&x[0] = *(const float4*)(rp);
    *(float4*)&x[4] = *(const float4*)(rp + 4);
    const float* hp = state + (size_t)b * RU + u * MM;
    *(float4*)&h[0] = *(const float4*)(hp);
    *(float4*)&h[4] = *(const float4*)(hp + 4);

    float e[8], mx = -1e30f;
#pragma unroll
    for (int m = 0; m < 8; m++) {
        float d = x[m] - LN_TAU_STEP * (float)m;
        e[m] = -d * d;
        mx = fmaxf(mx, e[m]);
    }
    float s = 0.0f, qsum = 0.0f;
#pragma unroll
    for (int m = 0; m < 8; m++) {
        float w = __expf(e[m] - mx);
        s += w;
        qsum = fmaf(w, h[m], qsum);
    }
    float qv = qsum / s;
    float a = g_alR[b];
    int8_t c0, c1;
    quant2(qv, a, 1.0f / a, c0, c1);
    size_t ba = (size_t)b * AROW;
    g_Ar[ba + 512 + u]  = c0;
    g_Ar[ba + 1536 + u] = c1;
}

// ---------------------------------------------------------------------------
// final: dpre = alR*beD*(P0 + (P1a+P1b)/256) + b_d; tanh; update gate; decay.
// ---------------------------------------------------------------------------
__global__ void final_kernel(const float* __restrict__ state,
                             const float* __restrict__ elapsed,
                             const float* __restrict__ b_d,
                             float* __restrict__ out_h,
                             float* __restrict__ out_hh)
{
    int idx = blockIdx.x * blockDim.x + threadIdx.x;
    if (idx >= BB * UU) return;
    int b = idx >> 9;
    int u = idx & 511;

    const float invtau[8] = {1.0f, 0.31622776601683794f, 0.1f,
                             0.03162277660168379f, 0.01f,
                             0.003162277660168379f, 0.001f,
                             0.00031622776601683794f};

    const size_t NP = (size_t)BB * UU;
    float dpre = g_alR[b] * g_beD[u] *
                 (g_pd[idx] + (g_pd[idx + NP] + g_pd[idx + 2 * NP]) * (1.0f / 256.0f))
               + b_d[u];
    float qk = tanhf(dpre);

    const float* up = g_u + (size_t)b * RU + u * MM;
    float x[8], h[8];
    *(float4*)&x[0] = *(const float4*)(up);
    *(float4*)&x[4] = *(const float4*)(up + 4);
    const float* hp = state + (size_t)b * RU + u * MM;
    *(float4*)&h[0] = *(const float4*)(hp);
    *(float4*)&h[4] = *(const float4*)(hp + 4);

    float e[8], mx = -1e30f;
#pragma unroll
    for (int m = 0; m < 8; m++) {
        float d = x[m] - LN_TAU_STEP * (float)m;
        e[m] = -d * d;
        mx = fmaxf(mx, e[m]);
    }
    float w[8], s = 0.0f;
#pragma unroll
    for (int m = 0; m < 8; m++) { w[m] = __expf(e[m] - mx); s += w[m]; }
    float inv_s = 1.0f / s;
    float el = elapsed[b];

    float hh[8], hn = 0.0f;
#pragma unroll
    for (int m = 0; m < 8; m++) {
        float ski = w[m] * inv_s;
        float dec = __expf(-el * invtau[m]);
        hh[m] = ((1.0f - ski) * h[m] + ski * qk) * dec;
        hn += hh[m];
    }
    float* op = out_hh + (size_t)b * RU + u * MM;
    *(float4*)(op)     = *(const float4*)&hh[0];
    *(float4*)(op + 4) = *(const float4*)&hh[4];
    if (out_h) out_h[(size_t)b * UU + u] = hn;
}

// ---------------------------------------------------------------------------
extern "C" void kernel_launch(void* const* d_in, const int* in_sizes, int n_in,
                              void* d_out, int out_size)
{
    const float* inputs  = (const float*)d_in[0];
    const float* elapsed = (const float*)d_in[1];
    const float* state   = (const float*)d_in[2];
    const float* W_r     = (const float*)d_in[3];
    const float* b_r     = (const float*)d_in[4];
    const float* W_d     = (const float*)d_in[5];
    const float* b_d     = (const float*)d_in[6];
    const float* W_u     = (const float*)d_in[7];
    const float* b_u     = (const float*)d_in[8];

    float* out = (float*)d_out;
    float* out_h;
    float* out_hh;
    if (out_size == BB * UU * MM) { out_h = nullptr; out_hh = out; }
    else { out_h = out; out_hh = out + (size_t)BB * UU; }

    int8_t *p_Af, *p_Ar, *p_Wr, *p_Wu, *p_Wd;
    float *p_alF, *p_alR, *p_beR, *p_beU, *p_beD, *p_r, *p_u, *p_pd;
    cudaGetSymbolAddress((void**)&p_Af, g_Af);
    cudaGetSymbolAddress((void**)&p_Ar, g_Ar);
    cudaGetSymbolAddress((void**)&p_Wr, g_Wr);
    cudaGetSymbolAddress((void**)&p_Wu, g_Wu);
    cudaGetSymbolAddress((void**)&p_Wd, g_Wd);
    cudaGetSymbolAddress((void**)&p_alF, g_alF);
    cudaGetSymbolAddress((void**)&p_alR, g_alR);
    cudaGetSymbolAddress((void**)&p_beR, g_beR);
    cudaGetSymbolAddress((void**)&p_beU, g_beU);
    cudaGetSymbolAddress((void**)&p_beD, g_beD);
    cudaGetSymbolAddress((void**)&p_r,   g_r);
    cudaGetSymbolAddress((void**)&p_u,   g_u);
    cudaGetSymbolAddress((void**)&p_pd,  g_pd);

    cudaFuncSetAttribute(gemm_s8_kernel,
                         cudaFuncAttributeMaxDynamicSharedMemorySize, S8_SMEM);

    quant_setup_kernel<<<2320, 256>>>(inputs, state, W_r, W_u, W_d);

    // R (z=0) and U (z=1) in one launch, shared A
    gemm_s8_kernel<<<dim3(32, 8, 2), 512, S8_SMEM>>>(
        p_Af, p_Wr, p_Wu, p_alF, p_beR, p_beU, b_r, b_u, p_r, p_u, RU, 0);

    gate_r_kernel<<<(BB * UU + 255) / 256, 256>>>(state);

    // D: 3 balanced 8-iter K-slices -> raw partials
    gemm_s8_kernel<<<dim3(4, 8, 3), 512, S8_SMEM>>>(
        p_Ar, p_Wd, nullptr, p_alR, p_beD, nullptr, nullptr, nullptr,
        p_pd, nullptr, UU, 1);

    final_kernel<<<(BB * UU + 255) / 256, 256>>>(state, elapsed, b_d, out_h, out_hh);
}

// round 16
// speedup vs baseline: 2.1012x; 2.1012x over previous
#include <cuda_runtime.h>
#include <cuda_bf16.h>
#include <cstdint>
#include <math.h>

// ---------------------------------------------------------------------------
// CT-GRU round 16: bf16 split GEMMs (K'=3072), BM=128 BN=128 BK=64,
// 256 threads / 8 warps / warp tile 64x32, 2 CTAs per SM, 3-stage cp.async.
// R+U merged in one launch (z=2); D k-split x4. Elementwise kernels separate.
// ---------------------------------------------------------------------------

#define BB 2048
#define UU 512
#define MM 8
#define DD 512
#define FD 1024
#define RU 4096          // U*M
#define KTOT 3072        // 3 * FD (split-K)

#define LN_TAU_STEP 1.1512925464970229f

__device__ __nv_bfloat16 g_Af[(size_t)BB * KTOT];
__device__ __nv_bfloat16 g_Ar[(size_t)BB * KTOT];
__device__ __nv_bfloat16 g_Wr[(size_t)RU * KTOT];
__device__ __nv_bfloat16 g_Wu[(size_t)RU * KTOT];
__device__ __nv_bfloat16 g_Wd[(size_t)UU * KTOT];
__device__ float g_r[(size_t)BB * RU];
__device__ float g_u[(size_t)BB * RU];
__device__ float g_dpre[4 * (size_t)BB * UU];

__device__ __forceinline__ uint32_t smem_u32(const void* p) {
    uint32_t a;
    asm("{ .reg .u64 t; cvta.to.shared.u64 t, %1; cvt.u32.u64 %0, t; }"
        : "=r"(a) : "l"(p));
    return a;
}
__device__ __forceinline__ void ldsm_x4(uint32_t* r, uint32_t addr) {
    asm volatile("ldmatrix.sync.aligned.m8n8.x4.shared.b16 {%0,%1,%2,%3}, [%4];"
        : "=r"(r[0]), "=r"(r[1]), "=r"(r[2]), "=r"(r[3]) : "r"(addr));
}
__device__ __forceinline__ void mma_bf16(float* d, const uint32_t* a,
                                         uint32_t b0, uint32_t b1) {
    asm volatile("mma.sync.aligned.m16n8k16.row.col.f32.bf16.bf16.f32 "
        "{%0,%1,%2,%3}, {%4,%5,%6,%7}, {%8,%9}, {%0,%1,%2,%3};"
        : "+f"(d[0]), "+f"(d[1]), "+f"(d[2]), "+f"(d[3])
        : "r"(a[0]), "r"(a[1]), "r"(a[2]), "r"(a[3]), "r"(b0), "r"(b1));
}
__device__ __forceinline__ void cp16(uint32_t dst, const void* src) {
    asm volatile("cp.async.cg.shared.global [%0], [%1], 16;" :: "r"(dst), "l"(src));
}
#define CP_COMMIT() asm volatile("cp.async.commit_group;" ::: "memory")
#define CP_WAIT(n)  asm volatile("cp.async.wait_group %0;" :: "n"(n) : "memory")

__device__ __forceinline__ uint32_t swz(int row, int chunk) {
    return (uint32_t)(row * 128 + ((chunk ^ (row & 7)) << 4));
}

// ---------------------------------------------------------------------------
// setup: z=0..2 -> weight convert/transpose; z=3 -> prep (A-side bf16 splits)
// ---------------------------------------------------------------------------
__global__ void setup_kernel(const float* __restrict__ inputs,
                             const float* __restrict__ state,
                             const float* __restrict__ W_r,
                             const float* __restrict__ W_u,
                             const float* __restrict__ W_d)
{
    const int z = blockIdx.z;
    const int tx = threadIdx.x, ty = threadIdx.y;

    if (z == 3) {
        int bl = blockIdx.y * 128 + blockIdx.x;
        int idx = bl * 256 + ty * 32 + tx;
        int b = idx >> 9;
        int j = idx & 511;

        float x = inputs[(size_t)b * DD + j];
        __nv_bfloat16 xh = __float2bfloat16_rn(x);
        __nv_bfloat16 xl = __float2bfloat16_rn(x - __bfloat162float(xh));

        size_t base = (size_t)b * KTOT;
        g_Af[base + j]        = xh;
        g_Af[base + 1024 + j] = xh;
        g_Af[base + 2048 + j] = xl;
        g_Ar[base + j]        = xh;
        g_Ar[base + 1024 + j] = xh;
        g_Ar[base + 2048 + j] = xl;

        const float* hp = state + (size_t)b * RU + j * MM;
        float4 h0 = *(const float4*)(hp);
        float4 h1 = *(const float4*)(hp + 4);
        float h = ((h0.x + h0.y) + (h0.z + h0.w)) + ((h1.x + h1.y) + (h1.z + h1.w));
        __nv_bfloat16 hh = __float2bfloat16_rn(h);
        __nv_bfloat16 hl = __float2bfloat16_rn(h - __bfloat162float(hh));
        g_Af[base + 512 + j]        = hh;
        g_Af[base + 1024 + 512 + j] = hh;
        g_Af[base + 2048 + 512 + j] = hl;
        return;
    }

    const float* W;
    __nv_bfloat16* Wt;
    int Ndim;
    if (z == 0)      { W = W_r; Wt = g_Wr; Ndim = RU; }
    else if (z == 1) { W = W_u; Wt = g_Wu; Ndim = RU; }
    else             { W = W_d; Wt = g_Wd; Ndim = UU; }
    if (blockIdx.x * 32 >= Ndim) return;

    __shared__ float t[32][33];
    int n0 = blockIdx.x * 32;
    int k0 = blockIdx.y * 32;

#pragma unroll
    for (int i = 0; i < 4; i++) {
        int k = k0 + ty + i * 8;
        t[ty + i * 8][tx] = W[(size_t)k * Ndim + n0 + tx];
    }
    __syncthreads();

#pragma unroll
    for (int i = 0; i < 4; i++) {
        int r = ty + i * 8;
        float v = t[tx][r];
        __nv_bfloat16 vh = __float2bfloat16_rn(v);
        __nv_bfloat16 vl = __float2bfloat16_rn(v - __bfloat162float(vh));
        size_t base = (size_t)(n0 + r) * KTOT + k0 + tx;
        Wt[base]        = vh;
        Wt[base + 1024] = vl;
        Wt[base + 2048] = vh;
    }
}

// ---------------------------------------------------------------------------
// HMMA GEMM: BM=128, BN=128, BK=64, 256 threads (8 warps 2x4),
// warp tile 64x32, 2 CTAs/SM, 3-stage cp.async, 1 sync per iter.
// mode 0: z picks {W0,bias0,C0} / {W1,bias1,C1}, full K (48 iters).
// mode 1: z = k-slice (12 iters each), raw partials into C0 + z*BB*UU.
// ---------------------------------------------------------------------------
#define GBM 128
#define GBN 128
#define GBK 64
#define NIT 48
#define STG 32768u           // A 16KB + B 16KB
#define NSTAGE 3
#define GEMM_SMEM (NSTAGE * STG)   // 98304

__global__ void __launch_bounds__(256, 2)
gemm_mma_kernel(const __nv_bfloat16* __restrict__ A,
                const __nv_bfloat16* __restrict__ W0,
                const __nv_bfloat16* __restrict__ W1,
                const float* __restrict__ bias0,
                const float* __restrict__ bias1,
                float* __restrict__ C0,
                float* __restrict__ C1,
                int Ndim, int mode)
{
    extern __shared__ char smem[];
    const uint32_t sb = smem_u32(smem);
    const int tid = threadIdx.x;
    const int wid = tid >> 5;
    const int lane = tid & 31;
    const int bn = blockIdx.x * GBN;
    const int bm = blockIdx.y * GBM;
    const int z = blockIdx.z;

    const __nv_bfloat16* Bt;
    const float* bias;
    float* C;
    int kbeg, kend;
    if (mode == 0) {
        Bt = z ? W1 : W0; bias = z ? bias1 : bias0; C = z ? C1 : C0;
        kbeg = 0; kend = NIT;
    } else {
        Bt = W0; bias = nullptr;
        C = C0 + (size_t)z * ((size_t)BB * UU);
        kbeg = 12 * z; kend = kbeg + 12;
    }

    const int warp_m = (wid & 1) * 64;      // 0,64
    const int warp_n = (wid >> 1) * 32;     // 0,32,64,96

    float acc[4][4][4];
#pragma unroll
    for (int i = 0; i < 4; i++)
#pragma unroll
        for (int j = 0; j < 4; j++)
#pragma unroll
            for (int v = 0; v < 4; v++) acc[i][j][v] = 0.0f;

    // linearized loader: granule slot s: row = (tid>>3) + 32*s, ch = tid&7
    // (row&7 invariant across s since 32 % 8 == 0)
    const int r0 = tid >> 3, ch = tid & 7;
    const uint32_t dA = (uint32_t)(r0 * 128 + ((ch ^ (r0 & 7)) << 4));
    const uint32_t dB = 16384u + dA;
    const char* Ap = (const char*)A  + (size_t)(bm + r0) * (KTOT * 2) + ch * 16;
    const char* Bp = (const char*)Bt + (size_t)(bn + r0) * (KTOT * 2) + ch * 16;

    auto load_stage = [&](int it) {
        const uint32_t stg = sb + (uint32_t)(it % NSTAGE) * STG;
        const int off = it * 128;            // 64 bf16 = 128 B per iter
#pragma unroll
        for (int s = 0; s < 4; s++)
            cp16(stg + dA + (uint32_t)s * 4096u, Ap + off + (size_t)s * 32 * (KTOT * 2));
#pragma unroll
        for (int s = 0; s < 4; s++)
            cp16(stg + dB + (uint32_t)s * 4096u, Bp + off + (size_t)s * 32 * (KTOT * 2));
        CP_COMMIT();
    };

    load_stage(kbeg);
    load_stage(kbeg + 1);

#pragma unroll 1
    for (int it = kbeg; it < kend; it++) {
        if (it + 1 < kend) { CP_WAIT(1); } else { CP_WAIT(0); }
        __syncthreads();
        if (it + 2 < kend) load_stage(it + 2);

        const uint32_t abase = sb + (uint32_t)(it % NSTAGE) * STG;
        const uint32_t bbase = abase + 16384u;

#pragma unroll
        for (int kk = 0; kk < 4; kk++) {
            const int kch = kk * 2;
            uint32_t a[4][4];
#pragma unroll
            for (int mi = 0; mi < 4; mi++) {
                int row = warp_m + mi * 16 + (lane & 15);
                int c = kch + ((lane >> 4) & 1);
                ldsm_x4(a[mi], abase + swz(row, c));
            }
#pragma unroll
            for (int nb = 0; nb < 2; nb++) {
                uint32_t b[4];
                int row = warp_n + nb * 16 + (lane & 7) + (((lane >> 4) & 1) << 3);
                int c = kch + ((lane >> 3) & 1);
                ldsm_x4(b, bbase + swz(row, c));
#pragma unroll
                for (int mi = 0; mi < 4; mi++) {
                    mma_bf16(acc[mi][nb * 2 + 0], a[mi], b[0], b[1]);
                    mma_bf16(acc[mi][nb * 2 + 1], a[mi], b[2], b[3]);
                }
            }
        }
        // 3-stage ring: buffer overwritten by load(it+2) was last read at it-1
    }

    const int q  = lane & 3;
    const int rq = lane >> 2;
#pragma unroll
    for (int ni = 0; ni < 4; ni++) {
        int col = bn + warp_n + ni * 8 + q * 2;
        float bv0 = 0.0f, bv1 = 0.0f;
        if (bias) { bv0 = bias[col]; bv1 = bias[col + 1]; }
#pragma unroll
        for (int mi = 0; mi < 4; mi++) {
            int rr = bm + warp_m + mi * 16 + rq;
            float2 v0 = make_float2(acc[mi][ni][0] + bv0, acc[mi][ni][1] + bv1);
            float2 v1 = make_float2(acc[mi][ni][2] + bv0, acc[mi][ni][3] + bv1);
            *(float2*)(C + (size_t)rr * Ndim + col) = v0;
            *(float2*)(C + (size_t)(rr + 8) * Ndim + col) = v1;
        }
    }
}

// ---------------------------------------------------------------------------
__global__ void gate_r_kernel(const float* __restrict__ state)
{
    int idx = blockIdx.x * blockDim.x + threadIdx.x;
    if (idx >= BB * UU) return;
    int b = idx >> 9;
    int u = idx & 511;

    const float* rp = g_r + (size_t)b * RU + u * MM;
    float x[8], h[8];
    *(float4*)&x[0] = *(const float4*)(rp);
    *(float4*)&x[4] = *(const float4*)(rp + 4);
    const float* hp = state + (size_t)b * RU + u * MM;
    *(float4*)&h[0] = *(const float4*)(hp);
    *(float4*)&h[4] = *(const float4*)(hp + 4);

    float e[8], mx = -1e30f;
#pragma unroll
    for (int m = 0; m < 8; m++) {
        float d = x[m] - LN_TAU_STEP * (float)m;
        e[m] = -d * d;
        mx = fmaxf(mx, e[m]);
    }
    float s = 0.0f, qsum = 0.0f;
#pragma unroll
    for (int m = 0; m < 8; m++) {
        float w = __expf(e[m] - mx);
        s += w;
        qsum = fmaf(w, h[m], qsum);
    }
    float qv = qsum / s;
    __nv_bfloat16 qh = __float2bfloat16_rn(qv);
    __nv_bfloat16 ql = __float2bfloat16_rn(qv - __bfloat162float(qh));
    size_t base = (size_t)b * KTOT;
    g_Ar[base + 512 + u]        = qh;
    g_Ar[base + 1024 + 512 + u] = qh;
    g_Ar[base + 2048 + 512 + u] = ql;
}

// ---------------------------------------------------------------------------
__global__ void final_kernel(const float* __restrict__ state,
                             const float* __restrict__ elapsed,
                             const float* __restrict__ b_d,
                             float* __restrict__ out_h,
                             float* __restrict__ out_hh)
{
    int idx = blockIdx.x * blockDim.x + threadIdx.x;
    if (idx >= BB * UU) return;
    int b = idx >> 9;
    int u = idx & 511;

    const float invtau[8] = {1.0f, 0.31622776601683794f, 0.1f,
                             0.03162277660168379f, 0.01f,
                             0.003162277660168379f, 0.001f,
                             0.00031622776601683794f};

    const size_t NP = (size_t)BB * UU;
    float dpre = ((g_dpre[idx] + g_dpre[idx + NP])
               +  (g_dpre[idx + 2 * NP] + g_dpre[idx + 3 * NP])) + b_d[u];
    float qk = tanhf(dpre);

    const float* up = g_u + (size_t)b * RU + u * MM;
    float x[8], h[8];
    *(float4*)&x[0] = *(const float4*)(up);
    *(float4*)&x[4] = *(const float4*)(up + 4);
    const float* hp = state + (size_t)b * RU + u * MM;
    *(float4*)&h[0] = *(const float4*)(hp);
    *(float4*)&h[4] = *(const float4*)(hp + 4);

    float e[8], mx = -1e30f;
#pragma unroll
    for (int m = 0; m < 8; m++) {
        float d = x[m] - LN_TAU_STEP * (float)m;
        e[m] = -d * d;
        mx = fmaxf(mx, e[m]);
    }
    float w[8], s = 0.0f;
#pragma unroll
    for (int m = 0; m < 8; m++) { w[m] = __expf(e[m] - mx); s += w[m]; }
    float inv_s = 1.0f / s;
    float el = elapsed[b];

    float hh[8], hn = 0.0f;
#pragma unroll
    for (int m = 0; m < 8; m++) {
        float ski = w[m] * inv_s;
        float dec = __expf(-el * invtau[m]);
        hh[m] = ((1.0f - ski) * h[m] + ski * qk) * dec;
        hn += hh[m];
    }
    float* op = out_hh + (size_t)b * RU + u * MM;
    *(float4*)(op)     = *(const float4*)&hh[0];
    *(float4*)(op + 4) = *(const float4*)&hh[4];
    if (out_h) out_h[(size_t)b * UU + u] = hn;
}

// ---------------------------------------------------------------------------
extern "C" void kernel_launch(void* const* d_in, const int* in_sizes, int n_in,
                              void* d_out, int out_size)
{
    const float* inputs  = (const float*)d_in[0];
    const float* elapsed = (const float*)d_in[1];
    const float* state   = (const float*)d_in[2];
    const float* W_r     = (const float*)d_in[3];
    const float* b_r     = (const float*)d_in[4];
    const float* W_d     = (const float*)d_in[5];
    const float* b_d     = (const float*)d_in[6];
    const float* W_u     = (const float*)d_in[7];
    const float* b_u     = (const float*)d_in[8];

    float* out = (float*)d_out;
    float* out_h;
    float* out_hh;
    if (out_size == BB * UU * MM) { out_h = nullptr; out_hh = out; }
    else { out_h = out; out_hh = out + (size_t)BB * UU; }

    __nv_bfloat16 *p_Af, *p_Ar, *p_Wr, *p_Wu, *p_Wd;
    float *p_r, *p_u, *p_dpre;
    cudaGetSymbolAddress((void**)&p_Af, g_Af);
    cudaGetSymbolAddress((void**)&p_Ar, g_Ar);
    cudaGetSymbolAddress((void**)&p_Wr, g_Wr);
    cudaGetSymbolAddress((void**)&p_Wu, g_Wu);
    cudaGetSymbolAddress((void**)&p_Wd, g_Wd);
    cudaGetSymbolAddress((void**)&p_r,    g_r);
    cudaGetSymbolAddress((void**)&p_u,    g_u);
    cudaGetSymbolAddress((void**)&p_dpre, g_dpre);

    cudaFuncSetAttribute(gemm_mma_kernel,
                         cudaFuncAttributeMaxDynamicSharedMemorySize, GEMM_SMEM);

    const int ew_blocks = (BB * UU + 255) / 256;

    setup_kernel<<<dim3(128, 32, 4), dim3(32, 8)>>>(inputs, state, W_r, W_u, W_d);

    // R (z=0) + U (z=1) in one launch; full K, fused bias
    gemm_mma_kernel<<<dim3(RU / GBN, BB / GBM, 2), 256, GEMM_SMEM>>>(
        p_Af, p_Wr, p_Wu, b_r, b_u, p_r, p_u, RU, 0);

    gate_r_kernel<<<ew_blocks, 256>>>(state);

    // D: k-split x4 into partials (summed with bias in final)
    gemm_mma_kernel<<<dim3(UU / GBN, BB / GBM, 4), 256, GEMM_SMEM>>>(
        p_Ar, p_Wd, nullptr, nullptr, nullptr, p_dpre, nullptr, UU, 1);

    final_kernel<<<ew_blocks, 256>>>(state, elapsed, b_d, out_h, out_hh);
}

// round 17
// speedup vs baseline: 2.8225x; 1.3433x over previous
#include <cuda_runtime.h>
#include <cuda_bf16.h>
#include <cstdint>
#include <math.h>

// ---------------------------------------------------------------------------
// CT-GRU round 17: round-9 proven kernel (BM=256, BK=128, 512 thr, 2-stage,
// linearized loader) + R/U merged into one z=2 launch for tail-wave overlap.
// GEMMs: split-bf16 K'=3072 = [hi|hi|lo] x [hi|lo|hi], mma.sync m16n8k16.
// ---------------------------------------------------------------------------

#define BB 2048
#define UU 512
#define MM 8
#define DD 512
#define FD 1024
#define RU 4096          // U*M
#define KTOT 3072        // 3 * FD (split-K)

#define LN_TAU_STEP 1.1512925464970229f

__device__ __nv_bfloat16 g_Af[(size_t)BB * KTOT];
__device__ __nv_bfloat16 g_Ar[(size_t)BB * KTOT];
__device__ __nv_bfloat16 g_Wr[(size_t)RU * KTOT];
__device__ __nv_bfloat16 g_Wu[(size_t)RU * KTOT];
__device__ __nv_bfloat16 g_Wd[(size_t)UU * KTOT];
__device__ float g_r[(size_t)BB * RU];
__device__ float g_u[(size_t)BB * RU];
__device__ float g_dpre[4 * (size_t)BB * UU];

__device__ __forceinline__ uint32_t smem_u32(const void* p) {
    uint32_t a;
    asm("{ .reg .u64 t; cvta.to.shared.u64 t, %1; cvt.u32.u64 %0, t; }"
        : "=r"(a) : "l"(p));
    return a;
}
__device__ __forceinline__ void ldsm_x4(uint32_t* r, uint32_t addr) {
    asm volatile("ldmatrix.sync.aligned.m8n8.x4.shared.b16 {%0,%1,%2,%3}, [%4];"
        : "=r"(r[0]), "=r"(r[1]), "=r"(r[2]), "=r"(r[3]) : "r"(addr));
}
__device__ __forceinline__ void mma_bf16(float* d, const uint32_t* a,
                                         uint32_t b0, uint32_t b1) {
    asm volatile("mma.sync.aligned.m16n8k16.row.col.f32.bf16.bf16.f32 "
        "{%0,%1,%2,%3}, {%4,%5,%6,%7}, {%8,%9}, {%0,%1,%2,%3};"
        : "+f"(d[0]), "+f"(d[1]), "+f"(d[2]), "+f"(d[3])
        : "r"(a[0]), "r"(a[1]), "r"(a[2]), "r"(a[3]), "r"(b0), "r"(b1));
}
__device__ __forceinline__ void cp16(uint32_t dst, const void* src) {
    asm volatile("cp.async.cg.shared.global [%0], [%1], 16;" :: "r"(dst), "l"(src));
}
#define CP_COMMIT() asm volatile("cp.async.commit_group;" ::: "memory")
#define CP_WAIT(n)  asm volatile("cp.async.wait_group %0;" :: "n"(n) : "memory")

__device__ __forceinline__ uint32_t swz(int row, int chunk) {
    return (uint32_t)(row * 128 + ((chunk ^ (row & 7)) << 4));
}

// ---------------------------------------------------------------------------
// setup: z=0..2 -> weight convert/transpose (Wr, Wu, Wd); z=3 -> prep
// grid (128, 32, 4), block (32, 8)
// ---------------------------------------------------------------------------
__global__ void setup_kernel(const float* __restrict__ inputs,
                             const float* __restrict__ state,
                             const float* __restrict__ W_r,
                             const float* __restrict__ W_u,
                             const float* __restrict__ W_d)
{
    const int z = blockIdx.z;
    const int tx = threadIdx.x, ty = threadIdx.y;

    if (z == 3) {
        int bl = blockIdx.y * 128 + blockIdx.x;
        int idx = bl * 256 + ty * 32 + tx;           // b*512 + j
        int b = idx >> 9;
        int j = idx & 511;

        float x = inputs[(size_t)b * DD + j];
        __nv_bfloat16 xh = __float2bfloat16_rn(x);
        __nv_bfloat16 xl = __float2bfloat16_rn(x - __bfloat162float(xh));

        size_t base = (size_t)b * KTOT;
        g_Af[base + j]        = xh;
        g_Af[base + 1024 + j] = xh;
        g_Af[base + 2048 + j] = xl;
        g_Ar[base + j]        = xh;
        g_Ar[base + 1024 + j] = xh;
        g_Ar[base + 2048 + j] = xl;

        const float* hp = state + (size_t)b * RU + j * MM;
        float4 h0 = *(const float4*)(hp);
        float4 h1 = *(const float4*)(hp + 4);
        float h = ((h0.x + h0.y) + (h0.z + h0.w)) + ((h1.x + h1.y) + (h1.z + h1.w));
        __nv_bfloat16 hh = __float2bfloat16_rn(h);
        __nv_bfloat16 hl = __float2bfloat16_rn(h - __bfloat162float(hh));
        g_Af[base + 512 + j]        = hh;
        g_Af[base + 1024 + 512 + j] = hh;
        g_Af[base + 2048 + 512 + j] = hl;
        return;
    }

    const float* W;
    __nv_bfloat16* Wt;
    int Ndim;
    if (z == 0)      { W = W_r; Wt = g_Wr; Ndim = RU; }
    else if (z == 1) { W = W_u; Wt = g_Wu; Ndim = RU; }
    else             { W = W_d; Wt = g_Wd; Ndim = UU; }
    if (blockIdx.x * 32 >= Ndim) return;

    __shared__ float t[32][33];
    int n0 = blockIdx.x * 32;
    int k0 = blockIdx.y * 32;

#pragma unroll
    for (int i = 0; i < 4; i++) {
        int k = k0 + ty + i * 8;
        t[ty + i * 8][tx] = W[(size_t)k * Ndim + n0 + tx];
    }
    __syncthreads();

#pragma unroll
    for (int i = 0; i < 4; i++) {
        int r = ty + i * 8;
        float v = t[tx][r];
        __nv_bfloat16 vh = __float2bfloat16_rn(v);
        __nv_bfloat16 vl = __float2bfloat16_rn(v - __bfloat162float(vh));
        size_t base = (size_t)(n0 + r) * KTOT + k0 + tx;
        Wt[base]        = vh;
        Wt[base + 1024] = vl;
        Wt[base + 2048] = vh;
    }
}

// ---------------------------------------------------------------------------
// HMMA GEMM: BM=256, BN=128, BK=128 (two 64-wide subtiles), 512 threads
// (16 warps 4x4), warp tile 64x32. 2-stage cp.async, 1 sync per iter,
// linearized loader addressing.
// mode 0: z picks {W0,bias0,C0} / {W1,bias1,C1}; full K (24 iters).
// mode 1: z = k-slice (6 iters each); raw partials into C0 + z*BB*UU.
// ---------------------------------------------------------------------------
#define GBM 256
#define GBN 128
#define GBK 128
#define NIT_FULL (KTOT / GBK)         // 24
#define STG_SUB 49152u                // per 64-subtile: A 32KB + B 16KB
#define STG   (2u * STG_SUB)          // 98304 per stage
#define GEMM_SMEM (2u * STG)          // 196608

__global__ void __launch_bounds__(512, 1)
gemm_mma_kernel(const __nv_bfloat16* __restrict__ A,
                const __nv_bfloat16* __restrict__ W0,
                const __nv_bfloat16* __restrict__ W1,
                const float* __restrict__ bias0,
                const float* __restrict__ bias1,
                float* __restrict__ C0,
                float* __restrict__ C1,
                int Ndim, int mode)
{
    extern __shared__ char smem[];
    const uint32_t sb = smem_u32(smem);
    const int tid = threadIdx.x;
    const int wid = tid >> 5;
    const int lane = tid & 31;
    const int bn = blockIdx.x * GBN;
    const int bm = blockIdx.y * GBM;
    const int z = blockIdx.z;

    const __nv_bfloat16* Bt;
    const float* bias;
    float* C;
    int kbeg, kend;
    if (mode == 0) {
        Bt = z ? W1 : W0; bias = z ? bias1 : bias0; C = z ? C1 : C0;
        kbeg = 0; kend = NIT_FULL;
    } else {
        Bt = W0; bias = nullptr;
        C = C0 + (size_t)z * ((size_t)BB * UU);
        kbeg = 6 * z; kend = kbeg + 6;
    }

    const int warp_m = (wid & 3) * 64;      // 0,64,128,192
    const int warp_n = (wid >> 2) * 32;     // 0,32,64,96

    float acc[4][4][4];
#pragma unroll
    for (int i = 0; i < 4; i++)
#pragma unroll
        for (int j = 0; j < 4; j++)
#pragma unroll
            for (int v = 0; v < 4; v++) acc[i][j][v] = 0.0f;

    // ---- linearized loader state ----
    // granule slot s: row = (tid>>4) + 32*s, sub = (tid>>3)&1, ch = tid&7
    // (row & 7 invariant in s since 32 % 8 == 0 -> swizzle term constant)
    const int r0  = tid >> 4;                // 0..31
    const int sub = (tid >> 3) & 1;
    const int ch  = tid & 7;
    const uint32_t dstA = (uint32_t)sub * STG_SUB
                        + (uint32_t)(r0 * 128) + (uint32_t)((ch ^ (r0 & 7)) << 4);
    const uint32_t dstB = dstA + 32768u;
    uint32_t a_src = (uint32_t)(r0 * 6144 + kbeg * 256 + sub * 128 + ch * 16);
    uint32_t b_src = a_src;
    const char* Abase = (const char*)A  + (size_t)bm * (KTOT * 2);
    const char* Bbase = (const char*)Bt + (size_t)bn * (KTOT * 2);

    auto load_stage = [&](uint32_t stg_base) {
        const char* As = Abase + a_src;
#pragma unroll
        for (int s = 0; s < 8; s++)
            cp16(stg_base + dstA + (uint32_t)s * 4096u, As + (size_t)s * 196608);
        const char* Bs = Bbase + b_src;
#pragma unroll
        for (int s = 0; s < 4; s++)
            cp16(stg_base + dstB + (uint32_t)s * 4096u, Bs + (size_t)s * 196608);
        CP_COMMIT();
        a_src += 256; b_src += 256;          // advance to next K-chunk
    };

    load_stage(sb);

#pragma unroll 1
    for (int it = kbeg; it < kend; it++) {
        const uint32_t buf = (uint32_t)(it - kbeg) & 1u;
        CP_WAIT(0);
        __syncthreads();
        if (it + 1 < kend) load_stage(sb + (buf ^ 1u) * STG);

        const uint32_t cbase = sb + buf * STG;
#pragma unroll
        for (int sh = 0; sh < 2; sh++) {      // two 64-wide subtiles
            const uint32_t abase = cbase + (uint32_t)sh * STG_SUB;
            const uint32_t bbase = abase + 32768u;
#pragma unroll
            for (int kk = 0; kk < 4; kk++) {  // k-steps of 16
                const int kch = kk * 2;
                uint32_t a[4][4];
#pragma unroll
                for (int mi = 0; mi < 4; mi++) {
                    int row = warp_m + mi * 16 + (lane & 15);
                    int c = kch + ((lane >> 4) & 1);
                    ldsm_x4(a[mi], abase + swz(row, c));
                }
#pragma unroll
                for (int nb = 0; nb < 2; nb++) {
                    uint32_t b[4];
                    int row = warp_n + nb * 16 + (lane & 7) + (((lane >> 4) & 1) << 3);
                    int c = kch + ((lane >> 3) & 1);
                    ldsm_x4(b, bbase + swz(row, c));
#pragma unroll
                    for (int mi = 0; mi < 4; mi++) {
                        mma_bf16(acc[mi][nb * 2 + 0], a[mi], b[0], b[1]);
                        mma_bf16(acc[mi][nb * 2 + 1], a[mi], b[2], b[3]);
                    }
                }
            }
        }
        // no trailing sync: next iter's wait+sync precedes any overwrite
    }

    // ---- epilogue (+bias if given) ----
    const int q  = lane & 3;
    const int rq = lane >> 2;
#pragma unroll
    for (int ni = 0; ni < 4; ni++) {
        int col = bn + warp_n + ni * 8 + q * 2;
        float bv0 = 0.0f, bv1 = 0.0f;
        if (bias) { bv0 = bias[col]; bv1 = bias[col + 1]; }
#pragma unroll
        for (int mi = 0; mi < 4; mi++) {
            int rr = bm + warp_m + mi * 16 + rq;
            float2 v0 = make_float2(acc[mi][ni][0] + bv0, acc[mi][ni][1] + bv1);
            float2 v1 = make_float2(acc[mi][ni][2] + bv0, acc[mi][ni][3] + bv1);
            *(float2*)(C + (size_t)rr * Ndim + col) = v0;
            *(float2*)(C + (size_t)(rr + 8) * Ndim + col) = v1;
        }
    }
}

// ---------------------------------------------------------------------------
__global__ void gate_r_kernel(const float* __restrict__ state)
{
    int idx = blockIdx.x * blockDim.x + threadIdx.x;
    if (idx >= BB * UU) return;
    int b = idx >> 9;
    int u = idx & 511;

    const float* rp = g_r + (size_t)b * RU + u * MM;
    float x[8], h[8];
    *(float4*)&x[0] = *(const float4*)(rp);
    *(float4*)&x[4] = *(const float4*)(rp + 4);
    const float* hp = state + (size_t)b * RU + u * MM;
    *(float4*)&h[0] = *(const float4*)(hp);
    *(float4*)&h[4] = *(const float4*)(hp + 4);

    float e[8], mx = -1e30f;
#pragma unroll
    for (int m = 0; m < 8; m++) {
        float d = x[m] - LN_TAU_STEP * (float)m;
        e[m] = -d * d;
        mx = fmaxf(mx, e[m]);
    }
    float s = 0.0f, qsum = 0.0f;
#pragma unroll
    for (int m = 0; m < 8; m++) {
        float w = __expf(e[m] - mx);
        s += w;
        qsum = fmaf(w, h[m], qsum);
    }
    float qv = qsum / s;
    __nv_bfloat16 qh = __float2bfloat16_rn(qv);
    __nv_bfloat16 ql = __float2bfloat16_rn(qv - __bfloat162float(qh));
    size_t base = (size_t)b * KTOT;
    g_Ar[base + 512 + u]        = qh;
    g_Ar[base + 1024 + 512 + u] = qh;
    g_Ar[base + 2048 + 512 + u] = ql;
}

// ---------------------------------------------------------------------------
__global__ void final_kernel(const float* __restrict__ state,
                             const float* __restrict__ elapsed,
                             const float* __restrict__ b_d,
                             float* __restrict__ out_h,
                             float* __restrict__ out_hh)
{
    int idx = blockIdx.x * blockDim.x + threadIdx.x;
    if (idx >= BB * UU) return;
    int b = idx >> 9;
    int u = idx & 511;

    const float invtau[8] = {1.0f, 0.31622776601683794f, 0.1f,
                             0.03162277660168379f, 0.01f,
                             0.003162277660168379f, 0.001f,
                             0.00031622776601683794f};

    const size_t NP = (size_t)BB * UU;
    float dpre = ((g_dpre[idx] + g_dpre[idx + NP])
               +  (g_dpre[idx + 2 * NP] + g_dpre[idx + 3 * NP])) + b_d[u];
    float qk = tanhf(dpre);

    const float* up = g_u + (size_t)b * RU + u * MM;
    float x[8], h[8];
    *(float4*)&x[0] = *(const float4*)(up);
    *(float4*)&x[4] = *(const float4*)(up + 4);
    const float* hp = state + (size_t)b * RU + u * MM;
    *(float4*)&h[0] = *(const float4*)(hp);
    *(float4*)&h[4] = *(const float4*)(hp + 4);

    float e[8], mx = -1e30f;
#pragma unroll
    for (int m = 0; m < 8; m++) {
        float d = x[m] - LN_TAU_STEP * (float)m;
        e[m] = -d * d;
        mx = fmaxf(mx, e[m]);
    }
    float w[8], s = 0.0f;
#pragma unroll
    for (int m = 0; m < 8; m++) { w[m] = __expf(e[m] - mx); s += w[m]; }
    float inv_s = 1.0f / s;
    float el = elapsed[b];

    float hh[8], hn = 0.0f;
#pragma unroll
    for (int m = 0; m < 8; m++) {
        float ski = w[m] * inv_s;
        float dec = __expf(-el * invtau[m]);
        hh[m] = ((1.0f - ski) * h[m] + ski * qk) * dec;
        hn += hh[m];
    }
    float* op = out_hh + (size_t)b * RU + u * MM;
    *(float4*)(op)     = *(const float4*)&hh[0];
    *(float4*)(op + 4) = *(const float4*)&hh[4];
    if (out_h) out_h[(size_t)b * UU + u] = hn;
}

// ---------------------------------------------------------------------------
extern "C" void kernel_launch(void* const* d_in, const int* in_sizes, int n_in,
                              void* d_out, int out_size)
{
    const float* inputs  = (const float*)d_in[0];
    const float* elapsed = (const float*)d_in[1];
    const float* state   = (const float*)d_in[2];
    const float* W_r     = (const float*)d_in[3];
    const float* b_r     = (const float*)d_in[4];
    const float* W_d     = (const float*)d_in[5];
    const float* b_d     = (const float*)d_in[6];
    const float* W_u     = (const float*)d_in[7];
    const float* b_u     = (const float*)d_in[8];

    float* out = (float*)d_out;
    float* out_h;
    float* out_hh;
    if (out_size == BB * UU * MM) { out_h = nullptr; out_hh = out; }
    else { out_h = out; out_hh = out + (size_t)BB * UU; }

    __nv_bfloat16 *p_Af, *p_Ar, *p_Wr, *p_Wu, *p_Wd;
    float *p_r, *p_u, *p_dpre;
    cudaGetSymbolAddress((void**)&p_Af, g_Af);
    cudaGetSymbolAddress((void**)&p_Ar, g_Ar);
    cudaGetSymbolAddress((void**)&p_Wr, g_Wr);
    cudaGetSymbolAddress((void**)&p_Wu, g_Wu);
    cudaGetSymbolAddress((void**)&p_Wd, g_Wd);
    cudaGetSymbolAddress((void**)&p_r,    g_r);
    cudaGetSymbolAddress((void**)&p_u,    g_u);
    cudaGetSymbolAddress((void**)&p_dpre, g_dpre);

    cudaFuncSetAttribute(gemm_mma_kernel,
                         cudaFuncAttributeMaxDynamicSharedMemorySize, GEMM_SMEM);

    const int ew_blocks = (BB * UU + 255) / 256;

    setup_kernel<<<dim3(128, 32, 4), dim3(32, 8)>>>(inputs, state, W_r, W_u, W_d);

    // R (z=0) + U (z=1) merged: 512 CTAs, tail-wave overlap
    gemm_mma_kernel<<<dim3(RU / GBN, BB / GBM, 2), 512, GEMM_SMEM>>>(
        p_Af, p_Wr, p_Wu, b_r, b_u, p_r, p_u, RU, 0);

    gate_r_kernel<<<ew_blocks, 256>>>(state);

    // D: k-split x4 into partials (summed with bias in final)
    gemm_mma_kernel<<<dim3(UU / GBN, BB / GBM, 4), 512, GEMM_SMEM>>>(
        p_Ar, p_Wd, nullptr, nullptr, nullptr, p_dpre, nullptr, UU, 1);

    final_kernel<<<ew_blocks, 256>>>(state, elapsed, b_d, out_h, out_hh);
}